// round 2
// baseline (speedup 1.0000x reference)
#include <cuda_runtime.h>
#include <math.h>

// Problem constants
#define NB    16          // batch
#define NDIM  256         // total channels
#define SS    64          // per-branch channels
#define NHEADS 4
#define HD    16
#define NPIX  4096        // 64*64
#define NBB   64          // NB * 4 branches

// ---------------- scratch (device globals; allocation-free rule) ----------
__device__ float g_y[(size_t)NB * NDIM * NPIX];          // post-dwconv, (bb,c,n)
__device__ float g_qkv[(size_t)NBB * 192 * NPIX];        // (bb, j, n), j: q 0..63, k 64..127, v 128..191
__device__ float g_M[4096];                              // per-column max of q
__device__ float g_Z[4096];                              // per-column sum exp of q
__device__ float g_ctx[(size_t)NBB * NHEADS * HD * HD];  // context / Z
__device__ float g_ao[(size_t)NBB * SS * NPIX];          // attention out pre-proj, scrambled layout (bb,c',n')
__device__ float g_cat[(size_t)NB * NDIM * NPIX];        // concat post-proj, (bb,c,n) == (b,256,n)

// ---------------- depthwise conv + bias + residual + relu -----------------
__global__ __launch_bounds__(256) void dwconv_kernel(
    const float* __restrict__ x,
    const float* __restrict__ w3, const float* __restrict__ b3,
    const float* __restrict__ w5, const float* __restrict__ b5,
    const float* __restrict__ w7, const float* __restrict__ b7,
    const float* __restrict__ w9, const float* __restrict__ b9)
{
    __shared__ float s[4096];
    __shared__ float ws[81];
    int bc = blockIdx.x;           // (b,cg): 0..4095
    int cg = bc & 255;
    int br = cg >> 6;
    int c  = cg & 63;
    const float* wsrc; const float* bsrc; int k;
    if (br == 0)      { wsrc = w3; bsrc = b3; k = 3; }
    else if (br == 1) { wsrc = w5; bsrc = b5; k = 5; }
    else if (br == 2) { wsrc = w7; bsrc = b7; k = 7; }
    else              { wsrc = w9; bsrc = b9; k = 9; }
    int t = threadIdx.x;
    const float* xp = x + (size_t)bc * NPIX;
    #pragma unroll
    for (int i = 0; i < 16; i++) s[t + i * 256] = xp[t + i * 256];
    if (t < k * k) ws[t] = wsrc[c * k * k + t];
    float bv = bsrc[c];
    __syncthreads();
    int r = k >> 1;
    for (int i = 0; i < 16; i++) {
        int p  = t + i * 256;
        int py = p >> 6, px = p & 63;
        float acc = 0.f;
        for (int u = 0; u < k; u++) {
            int yy = py + u - r;
            if ((unsigned)yy >= 64u) continue;
            const float* srow = &s[yy * 64];
            const float* wrow = &ws[u * k];
            for (int v = 0; v < k; v++) {
                int xx = px + v - r;
                if ((unsigned)xx >= 64u) continue;
                acc += srow[xx] * wrow[v];
            }
        }
        float o = acc + bv + s[p];
        g_y[(size_t)bc * NPIX + p] = fmaxf(o, 0.f);
    }
}

// ---------------- generic GEMM: C(m,j) = A(m,k) * W(j,k) ------------------
// A/C are "column-major within a 4096-row chunk": elem(m,k)=base[chunk*strideA + k*4096 + m%4096]
// 64x64x16 tile, 256 threads, 4x4 micro-tile.
__global__ __launch_bounds__(256) void gemm_cn(
    const float* __restrict__ A, const float* __restrict__ W,
    const float* __restrict__ bias, const float* __restrict__ scalew,
    float* __restrict__ C, int K, long chunkA, long chunkC)
{
    __shared__ float As[16][64];
    __shared__ float Ws[16][64];

    int m0    = blockIdx.x * 64;
    int chunk = m0 >> 12;
    int mloc  = m0 & 4095;
    int j0    = blockIdx.y * 64;

    const float* Ab = A + (size_t)chunk * chunkA + mloc;
    const float* Wb = W + (size_t)j0 * K;
    float*       Cb = C + (size_t)chunk * chunkC + mloc + (size_t)j0 * 4096;
    float scale = scalew ? scalew[chunk & 3] : 1.0f;

    int tid = threadIdx.x;
    int tr = tid >> 4, tc = tid & 15;
    int la_k = tid >> 4;            // 0..15
    int la_m = (tid & 15) * 4;      // 0..60
    int lw_j = tid >> 2;            // 0..63
    int lw_k = (tid & 3) * 4;       // 0..12

    float acc[4][4];
    #pragma unroll
    for (int i = 0; i < 4; i++)
        #pragma unroll
        for (int j = 0; j < 4; j++) acc[i][j] = 0.f;

    for (int k0 = 0; k0 < K; k0 += 16) {
        float4 av = *(const float4*)(Ab + (size_t)(k0 + la_k) * 4096 + la_m);
        *(float4*)&As[la_k][la_m] = av;
        float4 wv = *(const float4*)(Wb + (size_t)lw_j * K + k0 + lw_k);
        Ws[lw_k + 0][lw_j] = wv.x;
        Ws[lw_k + 1][lw_j] = wv.y;
        Ws[lw_k + 2][lw_j] = wv.z;
        Ws[lw_k + 3][lw_j] = wv.w;
        __syncthreads();
        #pragma unroll
        for (int kk = 0; kk < 16; kk++) {
            float4 a = *(const float4*)&As[kk][tr * 4];
            float4 b = *(const float4*)&Ws[kk][tc * 4];
            acc[0][0] += a.x * b.x; acc[0][1] += a.x * b.y; acc[0][2] += a.x * b.z; acc[0][3] += a.x * b.w;
            acc[1][0] += a.y * b.x; acc[1][1] += a.y * b.y; acc[1][2] += a.y * b.z; acc[1][3] += a.y * b.w;
            acc[2][0] += a.z * b.x; acc[2][1] += a.z * b.y; acc[2][2] += a.z * b.z; acc[2][3] += a.z * b.w;
            acc[3][0] += a.w * b.x; acc[3][1] += a.w * b.y; acc[3][2] += a.w * b.z; acc[3][3] += a.w * b.w;
        }
        __syncthreads();
    }

    #pragma unroll
    for (int jj = 0; jj < 4; jj++) {
        int j = tc * 4 + jj;
        float bj = bias ? bias[j0 + j] : 0.f;
        float4 o;
        o.x = (acc[0][jj] + bj) * scale;
        o.y = (acc[1][jj] + bj) * scale;
        o.z = (acc[2][jj] + bj) * scale;
        o.w = (acc[3][jj] + bj) * scale;
        *(float4*)(Cb + (size_t)j * 4096 + tr * 4) = o;
    }
}

// ---------------- softmax over hd=16 on K (in place) ----------------------
__global__ __launch_bounds__(256) void ksoftmax_kernel()
{
    int idx = blockIdx.x * 256 + threadIdx.x;   // 0 .. 64*4*4096-1
    int n  = idx & 4095;
    int hh = idx >> 12;                          // bb*4+h
    int bb = hh >> 2, h = hh & 3;
    float* base = g_qkv + ((size_t)(bb * 192 + 64 + h * 16)) * 4096 + n;
    float v[16];
    float mx = -3.4e38f;
    #pragma unroll
    for (int d = 0; d < 16; d++) { v[d] = base[(size_t)d * 4096]; mx = fmaxf(mx, v[d]); }
    float ssum = 0.f;
    #pragma unroll
    for (int d = 0; d < 16; d++) { v[d] = __expf(v[d] - mx); ssum += v[d]; }
    float inv = 1.0f / ssum;
    #pragma unroll
    for (int d = 0; d < 16; d++) base[(size_t)d * 4096] = v[d] * inv;
}

// ---------------- column stats (max, sumexp) over n for Q -----------------
__global__ __launch_bounds__(256) void qstats_kernel()
{
    __shared__ float red[256];
    int col = blockIdx.x;           // 0..4095 : bb*64 + j
    int bb = col >> 6, j = col & 63;
    const float* base = g_qkv + ((size_t)(bb * 192 + j)) * 4096;
    int t = threadIdx.x;
    float v[16];
    float mx = -3.4e38f;
    #pragma unroll
    for (int i = 0; i < 16; i++) { v[i] = base[t + i * 256]; mx = fmaxf(mx, v[i]); }
    red[t] = mx; __syncthreads();
    for (int s2 = 128; s2 > 0; s2 >>= 1) {
        if (t < s2) red[t] = fmaxf(red[t], red[t + s2]);
        __syncthreads();
    }
    mx = red[0]; __syncthreads();
    float sum = 0.f;
    #pragma unroll
    for (int i = 0; i < 16; i++) sum += __expf(v[i] - mx);
    red[t] = sum; __syncthreads();
    for (int s2 = 128; s2 > 0; s2 >>= 1) {
        if (t < s2) red[t] += red[t + s2];
        __syncthreads();
    }
    if (t == 0) { g_M[col] = mx; g_Z[col] = red[0]; }
}

// ---------------- context: C[d,e] = sum_n key[n,d] v[n,e], / Z ------------
__global__ __launch_bounds__(256) void context_kernel()
{
    __shared__ float ks[16][128];
    __shared__ float vs[16][128];
    int bh = blockIdx.x;            // bb*4+h
    int bb = bh >> 2, h = bh & 3;
    const float* kb = g_qkv + ((size_t)(bb * 192 + 64  + h * 16)) * 4096;
    const float* vb = g_qkv + ((size_t)(bb * 192 + 128 + h * 16)) * 4096;
    int t = threadIdx.x;
    int d = t >> 4, e = t & 15;
    float acc = 0.f;
    for (int n0 = 0; n0 < 4096; n0 += 128) {
        #pragma unroll
        for (int i = 0; i < 2; i++) {
            int idx = t * 2 + i;
            int row = idx >> 5;
            int c4  = (idx & 31) * 4;
            *(float4*)&ks[row][c4] = *(const float4*)(kb + (size_t)row * 4096 + n0 + c4);
            *(float4*)&vs[row][c4] = *(const float4*)(vb + (size_t)row * 4096 + n0 + c4);
        }
        __syncthreads();
        #pragma unroll
        for (int q4 = 0; q4 < 32; q4++) {
            float4 a = *(const float4*)&ks[d][q4 * 4];
            float4 b = *(const float4*)&vs[e][q4 * 4];
            acc += a.x * b.x + a.y * b.y + a.z * b.z + a.w * b.w;
        }
        __syncthreads();
    }
    float z = g_Z[bb * 64 + h * 16 + d];
    g_ctx[(size_t)bh * 256 + d * 16 + e] = acc / z;
}

// ---------------- attn out: ao = exp(q-M) @ ctx, with reference's raw
// (b,h,n,e)->(b,n,c) reshape folded into the store index:
//   pixel  n' = h*1024 + (n>>2)
//   chan   c' = 16*(n&3) + e
__global__ __launch_bounds__(256) void attnout_kernel()
{
    __shared__ float cs[1024];      // (h*16+d)*16+e
    __shared__ float ms[64];
    int bb = blockIdx.x >> 4;
    int nt = blockIdx.x & 15;
    int t  = threadIdx.x;
    int n  = nt * 256 + t;
    if (t < 64) ms[t] = g_M[bb * 64 + t];
    for (int i = t; i < 1024; i += 256) cs[i] = g_ctx[(size_t)bb * 1024 + i];
    __syncthreads();
    const float* qb = g_qkv + (size_t)bb * 192 * 4096 + n;
    int cbase = 16 * (n & 3);         // scrambled channel base
    int pbase = n >> 2;               // scrambled pixel base (before + h*1024)
    for (int h = 0; h < 4; h++) {
        float acc[16];
        #pragma unroll
        for (int e = 0; e < 16; e++) acc[e] = 0.f;
        #pragma unroll
        for (int d = 0; d < 16; d++) {
            int jc = h * 16 + d;
            float qv = __expf(qb[(size_t)jc * 4096] - ms[jc]);
            const float4* crow = (const float4*)&cs[jc * 16];
            #pragma unroll
            for (int e4 = 0; e4 < 4; e4++) {
                float4 cv = crow[e4];
                acc[e4 * 4 + 0] += qv * cv.x;
                acc[e4 * 4 + 1] += qv * cv.y;
                acc[e4 * 4 + 2] += qv * cv.z;
                acc[e4 * 4 + 3] += qv * cv.w;
            }
        }
        int np = h * 1024 + pbase;
        #pragma unroll
        for (int e = 0; e < 16; e++)
            g_ao[((size_t)(bb * 64 + cbase + e)) * 4096 + np] = acc[e];
    }
}

// ---------------- launch ---------------------------------------------------
extern "C" void kernel_launch(void* const* d_in, const int* in_sizes, int n_in,
                              void* d_out, int out_size)
{
    const float* x   = (const float*)d_in[0];
    const float* w3  = (const float*)d_in[1];
    const float* b3  = (const float*)d_in[2];
    const float* w5  = (const float*)d_in[3];
    const float* b5  = (const float*)d_in[4];
    const float* w7  = (const float*)d_in[5];
    const float* b7  = (const float*)d_in[6];
    const float* w9  = (const float*)d_in[7];
    const float* b9  = (const float*)d_in[8];
    const float* w_qkv   = (const float*)d_in[9];
    const float* w_proj  = (const float*)d_in[10];
    const float* b_proj  = (const float*)d_in[11];
    const float* w_final = (const float*)d_in[12];
    const float* b_final = (const float*)d_in[13];
    const float* scale_w = (const float*)d_in[14];
    float* out = (float*)d_out;

    float *yp, *qkvp, *aop, *catp;
    cudaGetSymbolAddress((void**)&yp,   g_y);
    cudaGetSymbolAddress((void**)&qkvp, g_qkv);
    cudaGetSymbolAddress((void**)&aop,  g_ao);
    cudaGetSymbolAddress((void**)&catp, g_cat);

    // 1. depthwise conv + bias + residual + relu  -> g_y (bb,c,n)
    dwconv_kernel<<<NB * NDIM, 256>>>(x, w3, b3, w5, b5, w7, b7, w9, b9);

    // 2. QKV GEMM: (262144 x 64) @ (192 x 64)^T -> g_qkv (bb,j,n)
    gemm_cn<<<dim3(262144 / 64, 3), 256>>>(yp, w_qkv, nullptr, nullptr, qkvp,
                                           64, 64L * 4096, 192L * 4096);

    // 3. softmax over hd for K (in place)
    ksoftmax_kernel<<<4096, 256>>>();

    // 4. column stats for Q softmax (axis = n)
    qstats_kernel<<<4096, 256>>>();

    // 5. context = key^T v, folded / Z
    context_kernel<<<256, 256>>>();

    // 6. attention out = exp(q - M) @ ctx  -> g_ao (scrambled reshape layout)
    attnout_kernel<<<1024, 256>>>();

    // 7. proj GEMM + bias + branch scale -> g_cat (b,256,n)
    gemm_cn<<<dim3(262144 / 64, 1), 256>>>(aop, w_proj, b_proj, scale_w, catp,
                                           64, 64L * 4096, 64L * 4096);

    // 8. final 1x1 conv: (65536 x 256) @ (256 x 256)^T + b_final -> d_out
    gemm_cn<<<dim3(65536 / 64, 4), 256>>>(catp, w_final, b_final, nullptr, out,
                                          256, 256L * 4096, 256L * 4096);
}